// round 6
// baseline (speedup 1.0000x reference)
#include <cuda_runtime.h>
#include <cuda_bf16.h>

// S4D: out[h,l] = 2*Re( sum_n Ceff[h,n] * exp(dtA[h,n]*l) )
// Per-n real 2-term recurrence y_{l+2} = a*y_{l+1} - b*y_l, packed f32x2 over
// n-pairs. 128 threads/block: group g in {0,1} owns 8 n-pairs; partial sums
// combined through double-buffered smem. Inner loops ordered t-outer/p-inner
// so consecutive instructions hit independent chains (ILP=8 in program order).

#define HH      1024
#define NH      32
#define LL      4096
#define THREADS 128
#define LTH     64          // threads spanning l per group
#define TPT     64          // l-values per thread
#define CH      8           // l per chunk
#define NCH     (TPT / CH)  // 8 chunks
#define NPG     8           // n-pairs per group (2 groups x 8 pairs = 32 n)

#define TWO_PI      6.283185307179586f
#define INV_TWO_PI  0.15915494309189535f

union F2U { float2 f; unsigned long long u; };

__device__ __forceinline__ float2 f2_fma(float2 a, float2 b, float2 c) {
    F2U A, B, C, D; A.f = a; B.f = b; C.f = c;
    asm("fma.rn.f32x2 %0, %1, %2, %3;" : "=l"(D.u) : "l"(A.u), "l"(B.u), "l"(C.u));
    return D.f;
}
__device__ __forceinline__ float2 f2_mul(float2 a, float2 b) {
    F2U A, B, D; A.f = a; B.f = b;
    asm("mul.rn.f32x2 %0, %1, %2;" : "=l"(D.u) : "l"(A.u), "l"(B.u));
    return D.f;
}
__device__ __forceinline__ float2 f2_add(float2 a, float2 b) {
    F2U A, B, D; A.f = a; B.f = b;
    asm("add.rn.f32x2 %0, %1, %2;" : "=l"(D.u) : "l"(A.u), "l"(B.u));
    return D.f;
}

__global__ __launch_bounds__(THREADS)
void s4d_kernel(const float* __restrict__ C_param,     // (H, 32, 2)
                const float* __restrict__ log_dt,      // (H,)
                const float* __restrict__ log_A_real,  // (H, 32)
                const float* __restrict__ A_imag,      // (H, 32)
                float* __restrict__ out)               // (H, L)
{
    __shared__ float s_a[NH], s_nb[NH];
    __shared__ float s_ur[NH], s_ui[NH], s_uwr[NH], s_uwi[NH];
    __shared__ float s_re[NH], s_turn[NH];
    __shared__ float s_red[2][LTH][CH];   // double-buffered partial sums

    const int h    = blockIdx.x;
    const int tid  = threadIdx.x;
    const int grp  = tid >> 6;            // 0 or 1: which 16 n's
    const int lane = tid & 63;            // which l-range

    // ---- per-(h,n) parameters (one warp; accurate libm ok here) ----
    if (tid < NH) {
        const int n  = tid;
        const int hn = h * NH + n;
        float dt = expf(log_dt[h]);
        float Ar = -expf(log_A_real[hn]);
        float Ai = A_imag[hn];
        float re = Ar * dt;                         // Re(dtA)  (<0)
        float im = Ai * dt;                         // Im(dtA)
        float er = expf(re);
        float si, co; sincosf(im, &si, &co);        // |im| small: fast path
        float wr = er * co, wi = er * si;           // w = exp(dtA)
        s_a[n]  = 2.0f * wr;
        s_nb[n] = -fmaf(wr, wr, wi * wi);           // -|w|^2
        // u = 2*C*(w-1)/A
        float numr = wr - 1.0f, numi = wi;
        float invd = 1.0f / fmaf(Ar, Ar, Ai * Ai);
        float tr = (numr * Ar + numi * Ai) * invd;
        float ti = (numi * Ar - numr * Ai) * invd;
        float Cr = C_param[2 * hn + 0];
        float Ci = C_param[2 * hn + 1];
        float ur = 2.0f * (Cr * tr - Ci * ti);
        float ui = 2.0f * (Cr * ti + Ci * tr);
        s_ur[n]  = ur;            s_ui[n]  = ui;
        s_uwr[n] = ur * wr - ui * wi;               // u*w
        s_uwi[n] = ur * wi + ui * wr;
        s_re[n]   = re;
        s_turn[n] = im * INV_TWO_PI;                // phase in turns per step
    }
    __syncthreads();

    // ---- seed recurrence at l0 = lane*TPT for this group's 16 n ----
    const float l0 = (float)(lane * TPT);
    const int   nbase = grp * 2 * NPG;              // first n of this group
    float2 Yp[NPG], Yc[NPG], A2[NPG], NB[NPG];

    #pragma unroll
    for (int p = 0; p < NPG; p++) {
        float y0v[2], y1v[2];
        #pragma unroll
        for (int k = 0; k < 2; k++) {
            const int n = nbase + 2 * p + k;
            float amp   = __expf(s_re[n] * l0);     // |w|^{l0}
            float turns = s_turn[n] * l0;
            float frac  = turns - truncf(turns);    // phase mod 1 turn
            float si, co; __sincosf(frac * TWO_PI, &si, &co);
            y0v[k] = amp * (s_ur[n]  * co - s_ui[n]  * si);  // Re(u*w^{l0})
            y1v[k] = amp * (s_uwr[n] * co - s_uwi[n] * si);  // Re(u*w^{l0+1})
        }
        Yp[p] = make_float2(y0v[0], y0v[1]);
        Yc[p] = make_float2(y1v[0], y1v[1]);
        A2[p] = make_float2(s_a[nbase + 2 * p],  s_a[nbase + 2 * p + 1]);
        NB[p] = make_float2(s_nb[nbase + 2 * p], s_nb[nbase + 2 * p + 1]);
    }

    float* orow = out + (size_t)h * LL + lane * TPT;

    // ---- main loop: 8 chunks of 8 l-values ----
    #pragma unroll 1
    for (int c = 0; c < NCH; c++) {
        float2 acc[CH];
        #pragma unroll
        for (int t = 0; t < CH; t++) acc[t] = make_float2(0.0f, 0.0f);

        // t-outer / p-inner: consecutive instrs hit independent chains
        #pragma unroll
        for (int t = 0; t < CH; t++) {
            #pragma unroll
            for (int p = 0; p < NPG; p++) {
                acc[t] = f2_add(acc[t], Yp[p]);      // out_l += y_l (pairwise)
                float2 tmp = f2_mul(NB[p], Yp[p]);   // -b * y_l (y_l ready early)
                float2 y2  = f2_fma(A2[p], Yc[p], tmp);
                Yp[p] = Yc[p]; Yc[p] = y2;
            }
        }

        // reduce pair lanes -> 8 scalars
        float r[CH];
        #pragma unroll
        for (int t = 0; t < CH; t++) r[t] = acc[t].x + acc[t].y;

        const int buf = c & 1;
        if (grp == 1) {
            *reinterpret_cast<float4*>(&s_red[buf][lane][0]) =
                make_float4(r[0], r[1], r[2], r[3]);
            *reinterpret_cast<float4*>(&s_red[buf][lane][4]) =
                make_float4(r[4], r[5], r[6], r[7]);
        }
        __syncthreads();
        if (grp == 0) {
            float4 p0 = *reinterpret_cast<const float4*>(&s_red[buf][lane][0]);
            float4 p1 = *reinterpret_cast<const float4*>(&s_red[buf][lane][4]);
            float4 o0 = make_float4(r[0] + p0.x, r[1] + p0.y,
                                    r[2] + p0.z, r[3] + p0.w);
            float4 o1 = make_float4(r[4] + p1.x, r[5] + p1.y,
                                    r[6] + p1.z, r[7] + p1.w);
            *reinterpret_cast<float4*>(orow + c * CH)     = o0;
            *reinterpret_cast<float4*>(orow + c * CH + 4) = o1;
        }
    }
}

extern "C" void kernel_launch(void* const* d_in, const int* in_sizes, int n_in,
                              void* d_out, int out_size) {
    const float* C_param    = (const float*)d_in[0];
    const float* log_dt     = (const float*)d_in[1];
    const float* log_A_real = (const float*)d_in[2];
    const float* A_imag     = (const float*)d_in[3];
    float* out = (float*)d_out;

    s4d_kernel<<<HH, THREADS>>>(C_param, log_dt, log_A_real, A_imag, out);
}